// round 16
// baseline (speedup 1.0000x reference)
#include <cuda_runtime.h>
#include <cuda.h>
#include <cuda_bf16.h>
#include <cuda_fp16.h>
#include <math.h>
#include <stdint.h>

#define EMBED 2048
#define NH 16
#define NKV 4
#define HD 128
#define FF 5632
#define BB 2
#define SS 2048
#define ROWS (BB*SS)                 // 4096 tokens
#define QKV_N ((NH + 2*NKV)*HD)      // 3072

#if defined(__CUDA_ARCH_FEAT_SM103_ALL) || defined(__CUDA_ARCH_FEAT_SM100_ALL)
#define USE_TCGEN05 1
#else
#define USE_TCGEN05 0
#endif

// 1/sqrt(EMBED) * log2(e): softmax done in exp2 domain
#define QSCALE (0.02209708691207961f * 1.4426950408889634f)

// ---------------- scratch (device globals; no allocations allowed) ----------
__device__ __half g_qkvh[ROWS*QKV_N];     // fp16 qkv gemm output (V region used)
__device__ __half g_qh2[BB*NH *SS*HD];    // fp16 Q (scaled), [b,h,s,d]
__device__ __half g_kh2[BB*NKV*SS*HD];    // fp16 K, [b,kvh,s,d]
__device__ __half g_vh2[BB*NKV*HD*SS];    // fp16 V transposed, [b,kvh,d,s]
__device__ float  g_h1 [ROWS*EMBED];
__device__ __half g_ah [ROWS*FF];         // fp16 activations (gemm A operand)
__device__ __half g_sw [ROWS*FF];         // fp16 fused-swiglu output (down-proj A)
__device__ __half g_wh [2*FF*EMBED];      // fp16 weights     (gemm B operand)

#define GM_STAGE_BYTES 65536              // A 32K + B 32K
#define GM_NSTAGE 3
#define GM_SMEM_BYTES (1024 + GM_NSTAGE*GM_STAGE_BYTES)

// ---------- common helpers (legal on plain sm_103 PTX) ----------------------
__device__ __forceinline__ uint32_t smem_u32(const void* p) {
    uint32_t a;
    asm("{ .reg .u64 t; cvta.to.shared.u64 t, %1; cvt.u32.u64 %0, t; }" : "=r"(a) : "l"(p));
    return a;
}
#define CP_COMMIT() asm volatile("cp.async.commit_group;" ::: "memory")
#define CP_WAIT0()  asm volatile("cp.async.wait_group 0;" ::: "memory")
#define CP_WAIT1()  asm volatile("cp.async.wait_group 1;" ::: "memory")
__device__ __forceinline__ void cpa16(uint32_t saddr, const void* g) {
    asm volatile("cp.async.cg.shared.global [%0], [%1], 16;" :: "r"(saddr), "l"(g) : "memory");
}
__device__ __forceinline__ void mma16816(float* c, const uint32_t* a, const uint32_t* b) {
    asm volatile("mma.sync.aligned.m16n8k16.row.col.f32.f16.f16.f32 "
        "{%0,%1,%2,%3}, {%4,%5,%6,%7}, {%8,%9}, {%0,%1,%2,%3};"
        : "+f"(c[0]), "+f"(c[1]), "+f"(c[2]), "+f"(c[3])
        : "r"(a[0]), "r"(a[1]), "r"(a[2]), "r"(a[3]), "r"(b[0]), "r"(b[1]));
}
__device__ __forceinline__ uint32_t ex2h2(uint32_t x) {
    uint32_t y; asm("ex2.approx.f16x2 %0, %1;" : "=r"(y) : "r"(x)); return y;
}
__device__ __forceinline__ float siluf(float a) {
    return a / (1.f + __expf(-a));
}

// ======================= fp32 -> fp16 convert (weights) ======================
__global__ __launch_bounds__(256) void conv_kernel(
    const float* __restrict__ x, __half* __restrict__ y, int n4)
{
    int i = blockIdx.x * 256 + threadIdx.x;
    if (i >= n4) return;
    float4 v = ((const float4*)x)[i];
    __half2* Y = (__half2*)y;
    Y[2*i]   = __floats2half2_rn(v.x, v.y);
    Y[2*i+1] = __floats2half2_rn(v.z, v.w);
}

// interleave rows: w1 row j -> dst row 2j, w2 row j -> dst row 2j+1
__global__ __launch_bounds__(256) void conv_inter_kernel(
    const float* __restrict__ w1, const float* __restrict__ w2,
    __half* __restrict__ y, int n4)   // n4 = FF*EMBED/4
{
    int i = blockIdx.x * 256 + threadIdx.x;
    if (i >= n4) return;
    const int RQ = EMBED / 4;
    int row = i / RQ, q = i % RQ;
    float4 a = ((const float4*)w1)[i];
    float4 b = ((const float4*)w2)[i];
    __half2* Y1 = (__half2*)(y + ((size_t)(2*row)   * EMBED) + q*4);
    __half2* Y2 = (__half2*)(y + ((size_t)(2*row+1) * EMBED) + q*4);
    Y1[0] = __floats2half2_rn(a.x, a.y);
    Y1[1] = __floats2half2_rn(a.z, a.w);
    Y2[0] = __floats2half2_rn(b.x, b.y);
    Y2[1] = __floats2half2_rn(b.z, b.w);
}

#if USE_TCGEN05
// ======================= tcgen05 GEMM + TMA multicast (sm_103a) ==============
__device__ __forceinline__ uint32_t cluster_rank() {
    uint32_t r; asm("mov.u32 %0, %%cluster_ctarank;" : "=r"(r)); return r;
}
#define MBAR_INIT(addr, cnt) \
    asm volatile("mbarrier.init.shared.b64 [%0], %1;" :: "r"(addr), "r"((uint32_t)(cnt)) : "memory")
#define MBAR_INVAL(addr) \
    asm volatile("mbarrier.inval.shared.b64 [%0];" :: "r"(addr) : "memory")
#define MBAR_EXPECT_TX(addr, bytes) \
    asm volatile("mbarrier.arrive.expect_tx.shared.b64 _, [%0], %1;" \
        :: "r"((uint32_t)(addr)), "r"((uint32_t)(bytes)) : "memory")
#define MBAR_WAIT(addr, parity) do { \
    uint32_t _m = (addr); uint32_t _p = (parity); uint32_t _d; \
    asm volatile("{\n\t.reg .pred p;\n\tmbarrier.try_wait.parity.acquire.cta.shared::cta.b64 p, [%1], %2;\n\tselp.b32 %0, 1, 0, p;\n\t}" \
        : "=r"(_d) : "r"(_m), "r"(_p) : "memory"); \
    if (!_d) { \
        asm volatile("{\n\t.reg .pred P1;\n\tWL_%=:\n\tmbarrier.try_wait.parity.acquire.cta.shared::cta.b64 P1, [%0], %1, 0x989680;\n\t@P1 bra.uni WD_%=;\n\tbra.uni WL_%=;\n\tWD_%=:\n\t}" \
            :: "r"(_m), "r"(_p) : "memory"); \
    } } while(0)
#define TC_ALLOC(smem_addr, n) \
    asm volatile("tcgen05.alloc.cta_group::1.sync.aligned.shared::cta.b32 [%0], %1;" \
        :: "r"((uint32_t)(smem_addr)), "r"((uint32_t)(n)) : "memory")
#define TC_DEALLOC(tmem_addr, n) \
    asm volatile("tcgen05.dealloc.cta_group::1.sync.aligned.b32 %0, %1;" :: "r"(tmem_addr), "r"((uint32_t)(n)))
#define TC_RELINQ() \
    asm volatile("tcgen05.relinquish_alloc_permit.cta_group::1.sync.aligned;")
#define TC_COMMIT(mbar) \
    asm volatile("tcgen05.commit.cta_group::1.mbarrier::arrive::one.shared::cluster.b64 [%0];" \
        :: "r"((uint32_t)(mbar)) : "memory")
#define TC_COMMIT_MC(mbar, mask) \
    asm volatile("tcgen05.commit.cta_group::1.mbarrier::arrive::one.shared::cluster.multicast::cluster.b64 [%0], %1;" \
        :: "r"((uint32_t)(mbar)), "h"((uint16_t)(mask)) : "memory")
#define TC_FENCE_AFTER() asm volatile("tcgen05.fence::after_thread_sync;" ::: "memory")
#define TC_FENCE_BEFORE() asm volatile("tcgen05.fence::before_thread_sync;" ::: "memory")
#define TC_WAIT_LD() asm volatile("tcgen05.wait::ld.sync.aligned;" ::: "memory")
#define CLUSTER_SYNC() do { \
    asm volatile("barrier.cluster.arrive.aligned;" ::: "memory"); \
    asm volatile("barrier.cluster.wait.aligned;" ::: "memory"); } while(0)
#define TMA_2D(smem, map, x, y, mbar) \
    asm volatile("cp.async.bulk.tensor.2d.shared::cta.global.tile.mbarrier::complete_tx::bytes " \
        "[%0], [%1, {%2, %3}], [%4];" \
        :: "r"((uint32_t)(smem)), "l"(map), "r"((int)(x)), "r"((int)(y)), "r"((uint32_t)(mbar)) : "memory")
#define TMA_2D_MC(smem, map, x, y, mbar, mask) \
    asm volatile("cp.async.bulk.tensor.2d.shared::cluster.global.tile.mbarrier::complete_tx::bytes.multicast::cluster " \
        "[%0], [%1, {%2, %3}], [%4], %5;" \
        :: "r"((uint32_t)(smem)), "l"(map), "r"((int)(x)), "r"((int)(y)), "r"((uint32_t)(mbar)), "h"((uint16_t)(mask)) : "memory")
#define TC_LD_X32(r, tmem_addr) \
    asm volatile("tcgen05.ld.sync.aligned.32x32b.x32.b32 " \
        "{%0, %1, %2, %3, %4, %5, %6, %7, %8, %9, %10, %11, %12, %13, %14, %15, " \
        " %16, %17, %18, %19, %20, %21, %22, %23, %24, %25, %26, %27, %28, %29, %30, %31}, [%32];" \
        : "=r"((r)[0]),  "=r"((r)[1]),  "=r"((r)[2]),  "=r"((r)[3]), \
          "=r"((r)[4]),  "=r"((r)[5]),  "=r"((r)[6]),  "=r"((r)[7]), \
          "=r"((r)[8]),  "=r"((r)[9]),  "=r"((r)[10]), "=r"((r)[11]), \
          "=r"((r)[12]), "=r"((r)[13]), "=r"((r)[14]), "=r"((r)[15]), \
          "=r"((r)[16]), "=r"((r)[17]), "=r"((r)[18]), "=r"((r)[19]), \
          "=r"((r)[20]), "=r"((r)[21]), "=r"((r)[22]), "=r"((r)[23]), \
          "=r"((r)[24]), "=r"((r)[25]), "=r"((r)[26]), "=r"((r)[27]), \
          "=r"((r)[28]), "=r"((r)[29]), "=r"((r)[30]), "=r"((r)[31]) \
        : "r"(tmem_addr))

__device__ __forceinline__ uint64_t mk_desc(uint32_t addr) {
    const uint64_t base = (2ull << 61) | (1ull << 46) | (64ull << 32) | (1ull << 16);
    return base | ((uint64_t)(addr >> 4) & 0x3FFF);
}
__device__ __forceinline__ void mma_f16_ss(uint32_t d, uint64_t da, uint64_t db,
                                           uint32_t idesc, uint32_t en) {
    asm volatile(
        "{\n\t.reg .pred p;\n\tsetp.ne.u32 p, %5, 0;\n\t"
        "tcgen05.mma.cta_group::1.kind::f16 [%0], %1, %2, %3, {%4,%4,%4,%4}, p;\n\t}"
        :: "r"(d), "l"(da), "l"(db), "r"(idesc), "r"(0u), "r"(en) : "memory");
}

#define GM_IDESC 0x8400010u              // F32 acc, fp16 a/b, M=128, N=256

// mode: 0 = fp32 out (+addend), 1 = fp16 out, 2 = fused silu, 3 = fused rope
__global__ __launch_bounds__(256, 1) void tc_gemm(
    const __grid_constant__ CUtensorMap mA, const __grid_constant__ CUtensorMap mB,
    const __half* __restrict__ A, const __half* __restrict__ B,
    float* __restrict__ Cf, __half* __restrict__ Ch,
    const float* __restrict__ addend,
    const float* __restrict__ freqs, __half* __restrict__ qh, __half* __restrict__ kh,
    int M, int N, int K, int mode)
{
    extern __shared__ char smem[];
    uint32_t sb = smem_u32(smem);
    int tid = threadIdx.x;
    int wid = tid >> 5, lane = tid & 31;
    int bn = blockIdx.x * 256, bm = blockIdx.y * 256;
    uint32_t rank = cluster_rank();     // cluster {1,2,1}: pair shares bn

    if (wid == 0) { TC_ALLOC(sb, 512); TC_RELINQ(); }
    if (tid == 0) {
        MBAR_INIT(sb + 8, 1);  MBAR_INIT(sb + 16, 1); MBAR_INIT(sb + 24, 1);  // full
        MBAR_INIT(sb + 32, 2); MBAR_INIT(sb + 40, 2);                          // done (2 commits)
        MBAR_INIT(sb + 48, 1);                                                 // final
    }
    __syncthreads();
    uint32_t tmem;
    asm volatile("ld.shared.b32 %0, [%1];" : "=r"(tmem) : "r"(sb));
    CLUSTER_SYNC();   // peer barriers initialized before any multicast

    const int NC = K / 64;
    if (tid == 0) {
        int phf[3] = {0, 0, 0};
        int phd0 = 0, phd1 = 0;
        #pragma unroll
        for (int c0 = 0; c0 < 2; c0++) {
            uint32_t stb = sb + 1024 + (uint32_t)c0 * GM_STAGE_BYTES;
            MBAR_EXPECT_TX(sb + 8 + c0*8, GM_STAGE_BYTES);
            TMA_2D(stb, &mA, c0*64, bm, sb + 8 + c0*8);
            if (rank == 0) TMA_2D_MC(stb + 32768, &mB, c0*64, bn, sb + 8 + c0*8, 3);
        }
        for (int c = 0; c < NC; c++) {
            int s = c % GM_NSTAGE;
            MBAR_WAIT(sb + 8 + s*8, phf[s]); phf[s] ^= 1;
            uint32_t stb = sb + 1024 + (uint32_t)s * GM_STAGE_BYTES;
            uint64_t dA0 = mk_desc(stb);
            uint64_t dA1 = mk_desc(stb + 16384);
            uint64_t dB  = mk_desc(stb + 32768);
            #pragma unroll
            for (int k = 0; k < 4; k++) {
                uint32_t en = (c > 0) || (k > 0);
                mma_f16_ss(tmem,       dA0 + k*2, dB + k*2, GM_IDESC, en);
                mma_f16_ss(tmem + 256, dA1 + k*2, dB + k*2, GM_IDESC, en);
            }
            TC_COMMIT_MC(sb + 32 + (uint32_t)(c & 1) * 8, 3);
            if (c == NC - 1) TC_COMMIT(sb + 48);
            if (c + 2 < NC) {
                if (c >= 1) {
                    int m = (c - 1) & 1;
                    if (m == 0) { MBAR_WAIT(sb + 32, phd0); phd0 ^= 1; }
                    else        { MBAR_WAIT(sb + 40, phd1); phd1 ^= 1; }
                }
                int s2 = (c + 2) % GM_NSTAGE;
                uint32_t stb2 = sb + 1024 + (uint32_t)s2 * GM_STAGE_BYTES;
                MBAR_EXPECT_TX(sb + 8 + s2*8, GM_STAGE_BYTES);
                TMA_2D(stb2, &mA, (c+2)*64, bm, sb + 8 + s2*8);
                if (rank == 0) TMA_2D_MC(stb2 + 32768, &mB, (c+2)*64, bn, sb + 8 + s2*8, 3);
            }
        }
    }
    MBAR_WAIT(sb + 48, 0);
    TC_FENCE_AFTER();

    int wg = wid >> 2, ws = wid & 3;
    #pragma unroll
    for (int h = 0; h < 2; h++) {
        size_t row = (size_t)(bm + h*128 + ws * 32 + lane);
        #pragma unroll
        for (int cb = 0; cb < 4; cb++) {
            uint32_t regs[32];
            TC_LD_X32(regs, tmem + (uint32_t)(h*256 + wg * 128 + cb * 32));
            TC_WAIT_LD();
            int col = bn + wg * 128 + cb * 32;
            if (mode == 3) {
                // fused rope/scatter for qkv output; thread's 32 cols in one head
                int s = (int)(row & (SS - 1));
                int b = (int)(row >> 11);
                const float* f = freqs + (size_t)s * HD;
                if (col < NH*HD) {              // Q: rotate + scale -> qh
                    int hh = col >> 7, d0 = col & 127;
                    __half* dst = qh + ((size_t)(b*NH + hh) * SS + s) * HD + d0;
                    __half2 o[16];
                    #pragma unroll
                    for (int t = 0; t < 16; t++) {
                        float x0 = __uint_as_float(regs[2*t]);
                        float x1 = __uint_as_float(regs[2*t+1]);
                        float cc = f[d0 + 2*t], sn = f[d0 + 2*t + 1];
                        o[t] = __floats2half2_rn((x0*cc - x1*sn) * QSCALE,
                                                 (x1*cc + x0*sn) * QSCALE);
                    }
                    *(uint4*)(dst)      = *(uint4*)&o[0];
                    *(uint4*)(dst + 8)  = *(uint4*)&o[4];
                    *(uint4*)(dst + 16) = *(uint4*)&o[8];
                    *(uint4*)(dst + 24) = *(uint4*)&o[12];
                } else if (col < (NH + NKV)*HD) {   // K: rotate -> kh
                    int hh = (col - NH*HD) >> 7, d0 = col & 127;
                    __half* dst = kh + ((size_t)(b*NKV + hh) * SS + s) * HD + d0;
                    __half2 o[16];
                    #pragma unroll
                    for (int t = 0; t < 16; t++) {
                        float x0 = __uint_as_float(regs[2*t]);
                        float x1 = __uint_as_float(regs[2*t+1]);
                        float cc = f[d0 + 2*t], sn = f[d0 + 2*t + 1];
                        o[t] = __floats2half2_rn(x0*cc - x1*sn, x1*cc + x0*sn);
                    }
                    *(uint4*)(dst)      = *(uint4*)&o[0];
                    *(uint4*)(dst + 8)  = *(uint4*)&o[4];
                    *(uint4*)(dst + 16) = *(uint4*)&o[8];
                    *(uint4*)(dst + 24) = *(uint4*)&o[12];
                } else {                        // V: plain fp16 to qkvh
                    __half* Cp = Ch + row * (size_t)N + col;
                    #pragma unroll
                    for (int j = 0; j < 32; j += 8) {
                        __half2 o[4];
                        o[0] = __floats2half2_rn(__uint_as_float(regs[j]),   __uint_as_float(regs[j+1]));
                        o[1] = __floats2half2_rn(__uint_as_float(regs[j+2]), __uint_as_float(regs[j+3]));
                        o[2] = __floats2half2_rn(__uint_as_float(regs[j+4]), __uint_as_float(regs[j+5]));
                        o[3] = __floats2half2_rn(__uint_as_float(regs[j+6]), __uint_as_float(regs[j+7]));
                        *(uint4*)(Cp + j) = *(uint4*)o;
                    }
                }
            } else if (mode == 2) {
                __half2 o[8];
                #pragma unroll
                for (int t = 0; t < 16; t += 2) {
                    float r0 = siluf(__uint_as_float(regs[2*t]))   * __uint_as_float(regs[2*t+1]);
                    float r1 = siluf(__uint_as_float(regs[2*t+2])) * __uint_as_float(regs[2*t+3]);
                    o[t >> 1] = __floats2half2_rn(r0, r1);
                }
                __half* Cp = Ch + row * (size_t)FF + (col >> 1);
                *(uint4*)(Cp)     = *(uint4*)&o[0];
                *(uint4*)(Cp + 8) = *(uint4*)&o[4];
            } else if (mode == 1) {
                __half* Cp = Ch + row * (size_t)N + col;
                #pragma unroll
                for (int j = 0; j < 32; j += 8) {
                    __half2 o[4];
                    o[0] = __floats2half2_rn(__uint_as_float(regs[j]),   __uint_as_float(regs[j+1]));
                    o[1] = __floats2half2_rn(__uint_as_float(regs[j+2]), __uint_as_float(regs[j+3]));
                    o[2] = __floats2half2_rn(__uint_as_float(regs[j+4]), __uint_as_float(regs[j+5]));
                    o[3] = __floats2half2_rn(__uint_as_float(regs[j+6]), __uint_as_float(regs[j+7]));
                    *(uint4*)(Cp + j) = *(uint4*)o;
                }
            } else {
                float* Cp = Cf + row * (size_t)N + col;
                if (addend) {
                    const float* Ap = addend + row * (size_t)N + col;
                    #pragma unroll
                    for (int j = 0; j < 32; j += 4) {
                        float4 a = *(const float4*)(Ap + j);
                        float4 o = make_float4(__uint_as_float(regs[j])   + a.x,
                                               __uint_as_float(regs[j+1]) + a.y,
                                               __uint_as_float(regs[j+2]) + a.z,
                                               __uint_as_float(regs[j+3]) + a.w);
                        *(float4*)(Cp + j) = o;
                    }
                } else {
                    #pragma unroll
                    for (int j = 0; j < 32; j += 4) {
                        float4 o = make_float4(__uint_as_float(regs[j]),
                                               __uint_as_float(regs[j+1]),
                                               __uint_as_float(regs[j+2]),
                                               __uint_as_float(regs[j+3]));
                        *(float4*)(Cp + j) = o;
                    }
                }
            }
        }
    }
    TC_FENCE_BEFORE();
    __syncthreads();
    if (tid == 0) {
        MBAR_INVAL(sb + 8);  MBAR_INVAL(sb + 16); MBAR_INVAL(sb + 24);
        MBAR_INVAL(sb + 32); MBAR_INVAL(sb + 40); MBAR_INVAL(sb + 48);
    }
    if (wid == 0) { TC_DEALLOC(tmem, 512); }
    CLUSTER_SYNC();
}

#else
// ======================= mma.sync GEMM fallback ==============================
#define FB_LD 40

__global__ __launch_bounds__(256, 1) void tc_gemm(
    const __grid_constant__ CUtensorMap mA, const __grid_constant__ CUtensorMap mB,
    const __half* __restrict__ A, const __half* __restrict__ B,
    float* __restrict__ Cf, __half* __restrict__ Ch,
    const float* __restrict__ addend,
    const float* __restrict__ freqs, __half* __restrict__ qh, __half* __restrict__ kh,
    int M, int N, int K, int mode)
{
    extern __shared__ char smem[];
    __half* sA = (__half*)smem;               // [128][40]
    __half* sB = sA + 128*FB_LD;              // [256][40]
    int tid = threadIdx.x, lane = tid & 31, wid = tid >> 5;
    int bn = blockIdx.x * 256;
    int wm = wid >> 2, wn = wid & 3;
    int g = lane >> 2, tig = lane & 3;

    for (int half = 0; half < 2; half++) {
        int bm = blockIdx.y * 256 + half * 128;
        float acc[4][8][4];
        #pragma unroll
        for (int mt = 0; mt < 4; mt++)
            #pragma unroll
            for (int nt = 0; nt < 8; nt++)
                #pragma unroll
                for (int q = 0; q < 4; q++) acc[mt][nt][q] = 0.f;

        for (int k0 = 0; k0 < K; k0 += 32) {
            __syncthreads();
            for (int v = tid; v < 512; v += 256) {
                int r = v >> 2, q = v & 3;
                *(uint4*)&sA[r*FB_LD + q*8] = *(const uint4*)(A + (size_t)(bm+r)*K + k0 + q*8);
            }
            for (int v = tid; v < 1024; v += 256) {
                int r = v >> 2, q = v & 3;
                *(uint4*)&sB[r*FB_LD + q*8] = *(const uint4*)(B + (size_t)(bn+r)*K + k0 + q*8);
            }
            __syncthreads();
            #pragma unroll
            for (int ks = 0; ks < 2; ks++) {
                int kk = ks * 16 + tig * 2;
                uint32_t a[4][4], b[8][2];
                #pragma unroll
                for (int mt = 0; mt < 4; mt++) {
                    int mr = (wm*64 + mt*16 + g)*FB_LD + kk;
                    a[mt][0] = *(const uint32_t*)&sA[mr];
                    a[mt][1] = *(const uint32_t*)&sA[mr + 8*FB_LD];
                    a[mt][2] = *(const uint32_t*)&sA[mr + 8];
                    a[mt][3] = *(const uint32_t*)&sA[mr + 8*FB_LD + 8];
                }
                #pragma unroll
                for (int nt = 0; nt < 8; nt++) {
                    int nr = (wn*64 + nt*8 + g)*FB_LD + kk;
                    b[nt][0] = *(const uint32_t*)&sB[nr];
                    b[nt][1] = *(const uint32_t*)&sB[nr + 8];
                }
                #pragma unroll
                for (int mt = 0; mt < 4; mt++)
                    #pragma unroll
                    for (int nt = 0; nt < 8; nt++)
                        mma16816(acc[mt][nt], a[mt], b[nt]);
            }
        }
        #pragma unroll
        for (int mt = 0; mt < 4; mt++) {
            #pragma unroll
            for (int nt = 0; nt < 8; nt++) {
                size_t r0 = (size_t)(bm + wm*64 + mt*16 + g);
                int col = bn + wn*64 + nt*8 + tig*2;
                if (mode == 3) {
                    #pragma unroll
                    for (int rr = 0; rr < 2; rr++) {
                        size_t row = r0 + rr*8;
                        float x0 = acc[mt][nt][2*rr], x1 = acc[mt][nt][2*rr+1];
                        int s = (int)(row & (SS-1)), b = (int)(row >> 11);
                        const float* f = freqs + (size_t)s * HD;
                        if (col < NH*HD) {
                            int hh = col >> 7, d0 = col & 127;
                            float cc = f[d0 & 126 ? d0 : d0], sn;   // placeholder
                            cc = f[(col & 127)]; sn = f[(col & 127) + 1];
                            *(__half2*)(qh + ((size_t)(b*NH + hh) * SS + s) * HD + (col & 127)) =
                                __floats2half2_rn((x0*cc - x1*sn) * QSCALE,
                                                  (x1*cc + x0*sn) * QSCALE);
                        } else if (col < (NH + NKV)*HD) {
                            int hh = (col - NH*HD) >> 7;
                            float cc = f[(col & 127)], sn = f[(col & 127) + 1];
                            *(__half2*)(kh + ((size_t)(b*NKV + hh) * SS + s) * HD + (col & 127)) =
                                __floats2half2_rn(x0*cc - x1*sn, x1*cc + x0*sn);
                        } else {
                            *(__half2*)(Ch + row*N + col) = __floats2half2_rn(x0, x1);
                        }
                    }
                } else if (mode == 2) {
                    float v0 = siluf(acc[mt][nt][0]) * acc[mt][nt][1];
                    float v1 = siluf(acc[mt][nt][2]) * acc[mt][nt][3];
                    Ch[r0*FF + (col>>1)]     = __float2half_rn(v0);
                    Ch[(r0+8)*FF + (col>>1)] = __float2half_rn(v1);
                } else if (mode == 1) {
                    *(__half2*)(Ch + r0*N + col)     = __floats2half2_rn(acc[mt][nt][0], acc[mt][nt][1]);
                    *(__half2*)(Ch + (r0+8)*N + col) = __floats2half2_rn(acc[mt][nt][2], acc[mt][nt][3]);
                } else {
                    float2 v0 = make_float2(acc[mt][nt][0], acc[mt][nt][1]);
                    float2 v1 = make_float2(acc[mt][nt][2], acc[mt][nt][3]);
                    if (addend) {
                        float2 a0 = *(const float2*)(addend + r0*N + col);
                        float2 a1 = *(const float2*)(addend + (r0+8)*N + col);
                        v0.x += a0.x; v0.y += a0.y; v1.x += a1.x; v1.y += a1.y;
                    }
                    *(float2*)(Cf + r0*N + col)     = v0;
                    *(float2*)(Cf + (r0+8)*N + col) = v1;
                }
            }
        }
        __syncthreads();
    }
}
#endif  // USE_TCGEN05

// ---------------- RMSNorm -> fp16 --------------------------------------------
__global__ __launch_bounds__(256) void rmsnorm_h_kernel(
    const float* __restrict__ x, const float* __restrict__ w,
    __half* __restrict__ out)
{
    __shared__ float red[8];
    int row = blockIdx.x;
    int tid = threadIdx.x;
    const float4* xr = (const float4*)(x + (size_t)row * EMBED);
    const float4* w4 = (const float4*)w;
    float4 v0 = xr[tid];
    float4 v1 = xr[tid + 256];
    float ss = v0.x*v0.x + v0.y*v0.y + v0.z*v0.z + v0.w*v0.w
             + v1.x*v1.x + v1.y*v1.y + v1.z*v1.z + v1.w*v1.w;
    #pragma unroll
    for (int o = 16; o > 0; o >>= 1) ss += __shfl_xor_sync(0xffffffffu, ss, o);
    if ((tid & 31) == 0) red[tid >> 5] = ss;
    __syncthreads();
    float tot = red[0] + red[1] + red[2] + red[3] + red[4] + red[5] + red[6] + red[7];
    float inv = rsqrtf(tot * (1.0f / EMBED) + 1e-5f);
    float4 wa = w4[tid], wb = w4[tid + 256];
    __half2* O = (__half2*)(out + (size_t)row * EMBED);
    O[2*tid]         = __floats2half2_rn(v0.x*inv*wa.x, v0.y*inv*wa.y);
    O[2*tid+1]       = __floats2half2_rn(v0.z*inv*wa.z, v0.w*inv*wa.w);
    O[2*(tid+256)]   = __floats2half2_rn(v1.x*inv*wb.x, v1.y*inv*wb.y);
    O[2*(tid+256)+1] = __floats2half2_rn(v1.z*inv*wb.z, v1.w*inv*wb.w);
}

// ---------------- Coalesced V transpose: [b,s,(kvh,d)] -> [b,kvh,d,s] --------
__global__ __launch_bounds__(256) void vtrans_kernel(
    const __half* __restrict__ qkv, __half* __restrict__ vh)
{
    __shared__ __half t[64*136];   // [64 s][128 d] padded
    int s0 = blockIdx.x * 64, h = blockIdx.y, b = blockIdx.z;
    int tid = threadIdx.x;
    const __half* src = qkv + ((size_t)b * SS + s0) * QKV_N + (size_t)(NH + NKV)*HD + h*HD;
    for (int i = tid; i < 64*16; i += 256) {
        int r = i >> 4, c = i & 15;
        *(uint4*)&t[r*136 + c*8] = *(const uint4*)(src + (size_t)r * QKV_N + c*8);
    }
    __syncthreads();
    __half* dst = vh + ((size_t)(b*NKV + h) * HD) * SS + s0;
    for (int i = tid; i < 128*8; i += 256) {
        int d = i >> 3, c = i & 7;
        __half v[8];
        #pragma unroll
        for (int j = 0; j < 8; j++) v[j] = t[(c*8 + j)*136 + d];
        *(uint4*)(dst + (size_t)d * SS + c*8) = *(uint4*)v;
    }
}

// ---------------- Tensor-core flash attention (fp16 mma, f16x2 exp2) ---------
#define FLH_SMEM_BYTES ((128*136 + 2*64*136 + 2*128*72) * 2)
__global__ __launch_bounds__(256) void flash_tc_kernel(
    const __half* __restrict__ qh, const __half* __restrict__ kh,
    const __half* __restrict__ vh, __half* __restrict__ oh)
{
    extern __shared__ __half smh[];
    __half* Qs  = smh;                      // [128][136]
    __half* Ks0 = Qs + 128*136;             // [64][136] x2
    __half* Ks1 = Ks0 + 64*136;
    __half* Vs0 = Ks1 + 64*136;             // [128][72] x2 (Vt: [d][kc])
    __half* Vs1 = Vs0 + 128*72;
    int tid = threadIdx.x, lane = tid & 31, wid = tid >> 5;
    int g = lane >> 2, tig = lane & 3;
    int qb = gridDim.x - 1 - blockIdx.x;    // biggest workload first
    int hb = blockIdx.y, bb = blockIdx.z;
    uint32_t ksb[2] = {smem_u32(Ks0), smem_u32(Ks1)};
    uint32_t vsb[2] = {smem_u32(Vs0), smem_u32(Vs1)};
    uint32_t qsb = smem_u32(Qs);

    const __half* Qg = qh + ((size_t)(bb*NH + hb) * SS + (size_t)qb*128) * HD;
    const __half* Kg = kh + (size_t)(bb*NKV + (hb >> 2)) * SS * HD;
    const __half* Vg = vh + (size_t)(bb*NKV + (hb >> 2)) * HD * SS;

    for (int i = tid; i < 128*16; i += 256) {
        int r = i >> 4, c = i & 15;
        cpa16(qsb + (uint32_t)(r*136 + c*8)*2, Qg + r*HD + c*8);
    }
    {   // stage 0
        for (int i = tid; i < 64*16; i += 256) {
            int r = i >> 4, c = i & 15;
            cpa16(ksb[0] + (uint32_t)(r*136 + c*8)*2, Kg + (size_t)r*HD + c*8);
        }
        for (int i = tid; i < 128*8; i += 256) {
            int r = i >> 3, c = i & 7;
            cpa16(vsb[0] + (uint32_t)(r*72 + c*8)*2, Vg + (size_t)r*SS + c*8);
        }
        CP_COMMIT();
    }

    float accO[16][4];
    #pragma unroll
    for (int nd = 0; nd < 16; nd++)
        #pragma unroll
        for (int q = 0; q < 4; q++) accO[nd][q] = 0.f;
    float accL[4] = {0.f, 0.f, 0.f, 0.f};
    const uint32_t ONES2 = 0x3C003C00u;
    uint32_t b_ones[2] = {ONES2, ONES2};
    int r0 = qb*128 + wid*16 + g;
    int r1 = r0 + 8;

    int nkb = 2*(qb + 1);
    for (int kb = 0; kb < nkb; kb++) {
        int st = kb & 1;
        if (kb + 1 < nkb) {
            int st2 = st ^ 1;
            for (int i = tid; i < 64*16; i += 256) {
                int r = i >> 4, c = i & 15;
                cpa16(ksb[st2] + (uint32_t)(r*136 + c*8)*2,
                      Kg + (size_t)((kb+1)*64 + r)*HD + c*8);
            }
            for (int i = tid; i < 128*8; i += 256) {
                int r = i >> 3, c = i & 7;
                cpa16(vsb[st2] + (uint32_t)(r*72 + c*8)*2,
                      Vg + (size_t)r*SS + (kb+1)*64 + c*8);
            }
            CP_COMMIT(); CP_WAIT1();
        } else {
            CP_WAIT0();
        }
        __syncthreads();
        const __half* Ks = (st == 0) ? Ks0 : Ks1;
        const __half* Vs = (st == 0) ? Vs0 : Vs1;

        float sacc[8][4];
        #pragma unroll
        for (int nt = 0; nt < 8; nt++)
            #pragma unroll
            for (int q = 0; q < 4; q++) sacc[nt][q] = 0.f;
        #pragma unroll
        for (int ks = 0; ks < 8; ks++) {
            uint32_t a[4];
            const __half* qr = &Qs[(wid*16 + g)*136 + ks*16 + 2*tig];
            a[0] = *(const uint32_t*)qr;
            a[1] = *(const uint32_t*)(qr + 8*136);
            a[2] = *(const uint32_t*)(qr + 8);
            a[3] = *(const uint32_t*)(qr + 8*136 + 8);
            #pragma unroll
            for (int nt = 0; nt < 8; nt++) {
                uint32_t b[2];
                const __half* kr = &Ks[(nt*8 + g)*136 + ks*16 + 2*tig];
                b[0] = *(const uint32_t*)kr;
                b[1] = *(const uint32_t*)(kr + 8);
                mma16816(sacc[nt], a, b);
            }
        }
        if (kb >= 2*qb) {
            #pragma unroll
            for (int nt = 0; nt < 8; nt++) {
                int col = kb*64 + nt*8 + 2*tig;
                if (col     > r0) sacc[nt][0] = -10000.f;
                if (col + 1 > r0) sacc[nt][1] = -10000.f;
                if (col     > r1) sacc[nt][2] = -10000.f;
                if (col + 1 > r1) sacc[nt][3] = -10000.f;
            }
        }
        #pragma unroll
        for (int j = 0; j < 4; j++) {
            uint32_t a[4];
            __half2 t;
            t = __floats2half2_rn(sacc[2*j][0],   sacc[2*j][1]);   a[0] = ex2h2(*(uint32_t*)&t);
            t = __floats2half2_rn(sacc[2*j][2],   sacc[2*j][3]);   a[1] = ex2h2(*(uint32_t*)&t);
            t = __floats2half2_rn(sacc[2*j+1][0], sacc[2*j+1][1]); a[2] = ex2h2(*(uint32_t*)&t);
            t = __floats2half2_rn(sacc[2*j+1][2], sacc[2*j+1][3]); a[3] = ex2h2(*(uint32_t*)&t);
            mma16816(accL, a, b_ones);
            #pragma unroll
            for (int nd = 0; nd < 16; nd++) {
                uint32_t b[2];
                const __half* vr = &Vs[(nd*8 + g)*72 + j*16 + 2*tig];
                b[0] = *(const uint32_t*)vr;
                b[1] = *(const uint32_t*)(vr + 8);
                mma16816(accO[nd], a, b);
            }
        }
        __syncthreads();
    }
    float inv0 = 1.f / accL[0], inv1 = 1.f / accL[2];
    __half* stg = smh;
    int lr = wid*16 + g;
    size_t obase = ((size_t)bb*SS + (size_t)qb*128) * EMBED + hb*HD;
    #pragma unroll
    for (int nd = 0; nd < 16; nd++) {
        int col = nd*8 + 2*tig;
        *(__half2*)&stg[lr*136 + col] =
            __floats2half2_rn(accO[nd][0]*inv0, accO[nd][1]*inv0);
        *(__half2*)&stg[(lr+8)*136 + col] =
            __floats2half2_rn(accO[nd][2]*inv1, accO[nd][3]*inv1);
    }
    __syncthreads();
    for (int i = tid; i < 128*16; i += 256) {
        int r = i >> 4, c = i & 15;
        *(uint4*)(oh + obase + (size_t)r*EMBED + c*8) = *(uint4*)&stg[r*136 + c*8];
    }
}

// ---------------- driver ------------------------------------------------------
typedef CUresult (CUDAAPI *tmap_fn_t)(
    CUtensorMap*, CUtensorMapDataType, cuuint32_t, void*,
    const cuuint64_t*, const cuuint64_t*, const cuuint32_t*, const cuuint32_t*,
    CUtensorMapInterleave, CUtensorMapSwizzle, CUtensorMapL2promotion,
    CUtensorMapFloatOOBfill);

static void make_map(tmap_fn_t fn, CUtensorMap* m, const __half* base,
                     uint64_t K, uint64_t rows)
{
    cuuint64_t dims[2]    = {(cuuint64_t)K, (cuuint64_t)rows};
    cuuint64_t strides[1] = {(cuuint64_t)(K * 2)};
    cuuint32_t box[2]     = {64, 256};
    cuuint32_t es[2]      = {1, 1};
    fn(m, CU_TENSOR_MAP_DATA_TYPE_FLOAT16, 2, (void*)base,
       dims, strides, box, es,
       CU_TENSOR_MAP_INTERLEAVE_NONE, CU_TENSOR_MAP_SWIZZLE_128B,
       CU_TENSOR_MAP_L2_PROMOTION_L2_128B, CU_TENSOR_MAP_FLOAT_OOB_FILL_NONE);
}

static inline void conv_launch(const float* src, __half* dst, size_t n)
{
    int n4 = (int)(n / 4);
    conv_kernel<<<(n4 + 255)/256, 256>>>(src, dst, n4);
}

static void gemm_launch(tmap_fn_t fn,
                        const __half* A, const __half* B,
                        float* Cf, __half* Ch, const float* addend,
                        const float* freqs, __half* qh, __half* kh,
                        int M, int N, int K, int mode, uint64_t Brows)
{
    CUtensorMap mA, mB;
    make_map(fn, &mA, A, (uint64_t)K, (uint64_t)M);
    make_map(fn, &mB, B, (uint64_t)K, Brows);
    cudaLaunchConfig_t cfg = {};
    cfg.gridDim = dim3(N/256, M/256);
    cfg.blockDim = dim3(256);
    cfg.dynamicSmemBytes = GM_SMEM_BYTES;
    cudaLaunchAttribute at[1];
    at[0].id = cudaLaunchAttributeClusterDimension;
    at[0].val.clusterDim.x = 1; at[0].val.clusterDim.y = 2; at[0].val.clusterDim.z = 1;
    cfg.attrs = at; cfg.numAttrs = 1;
    cudaLaunchKernelEx(&cfg, tc_gemm, mA, mB, A, B, Cf, Ch, addend,
                       freqs, qh, kh, M, N, K, mode);
}

extern "C" void kernel_launch(void* const* d_in, const int* in_sizes, int n_in,
                              void* d_out, int out_size)
{
    const float* x       = (const float*)d_in[0];
    const float* freqs   = (const float*)d_in[2];
    const float* w_qkv   = (const float*)d_in[4];
    const float* w_fc    = (const float*)d_in[5];
    const float* w1      = (const float*)d_in[6];
    const float* w2      = (const float*)d_in[7];
    const float* w3      = (const float*)d_in[8];
    const float* attn_nw = (const float*)d_in[9];
    const float* ff_nw   = (const float*)d_in[10];
    float* out = (float*)d_out;

    float *h1;
    __half *qkvh, *qh, *kh, *vh, *ah, *sw, *wh;
    cudaGetSymbolAddress((void**)&qkvh, g_qkvh);
    cudaGetSymbolAddress((void**)&qh,  g_qh2);
    cudaGetSymbolAddress((void**)&kh,  g_kh2);
    cudaGetSymbolAddress((void**)&vh,  g_vh2);
    cudaGetSymbolAddress((void**)&h1,  g_h1);
    cudaGetSymbolAddress((void**)&ah,  g_ah);
    cudaGetSymbolAddress((void**)&sw,  g_sw);
    cudaGetSymbolAddress((void**)&wh,  g_wh);

    void* pfn = nullptr;
    cudaDriverEntryPointQueryResult qr;
    cudaGetDriverEntryPointByVersion("cuTensorMapEncodeTiled", &pfn, 12000,
                                     cudaEnableDefault, &qr);
    tmap_fn_t fn = (tmap_fn_t)pfn;

    cudaFuncSetAttribute(tc_gemm, cudaFuncAttributeMaxDynamicSharedMemorySize, GM_SMEM_BYTES);
    cudaFuncSetAttribute(flash_tc_kernel, cudaFuncAttributeMaxDynamicSharedMemorySize, FLH_SMEM_BYTES);

    // 1. attn rmsnorm -> fp16
    rmsnorm_h_kernel<<<ROWS, 256>>>(x, attn_nw, ah);
    // 2. qkv projection with FUSED rope scatter (Q->qh, K->kh, V->qkvh)
    conv_launch(w_qkv, wh, (size_t)QKV_N*EMBED);
    gemm_launch(fn, ah, wh, nullptr, qkvh, nullptr, freqs, qh, kh,
                ROWS, QKV_N, EMBED, 3, QKV_N);
    // 3. coalesced V transpose
    vtrans_kernel<<<dim3(SS/64, NKV, BB), 256>>>(qkvh, vh);
    // 4. tensor-core flash attention -> fp16 attn into g_ah
    flash_tc_kernel<<<dim3(SS/128, NH, BB), 256, FLH_SMEM_BYTES>>>(qh, kh, vh, ah);
    // 5. output projection + residual -> fp32 h1
    conv_launch(w_fc, wh, (size_t)EMBED*EMBED);
    gemm_launch(fn, ah, wh, h1, nullptr, x, nullptr, nullptr, nullptr,
                ROWS, EMBED, EMBED, 0, EMBED);
    // 6. ffn rmsnorm -> fp16
    rmsnorm_h_kernel<<<ROWS, 256>>>(h1, ff_nw, ah);
    // 7. interleaved gate|up projection with FUSED swiglu -> g_sw
    {
        int n4 = FF*EMBED/4;
        conv_inter_kernel<<<(n4 + 255)/256, 256>>>(w1, w2, wh, n4);
    }
    gemm_launch(fn, ah, wh, nullptr, sw, nullptr, nullptr, nullptr, nullptr,
                ROWS, 2*FF, EMBED, 2, 2*FF);
    // 8. down projection + residual -> out
    conv_launch(w3, wh, (size_t)EMBED*FF);
    gemm_launch(fn, sw, wh, out, nullptr, h1, nullptr, nullptr, nullptr,
                ROWS, EMBED, FF, 0, EMBED);
}